// round 14
// baseline (speedup 1.0000x reference)
#include <cuda_runtime.h>

typedef unsigned long long u64;
typedef ulonglong2 ull2;
#define NSL 384
#define SLC 12800
#define ESL 160000
#define VN  400
#define CH  32
#define LL  12

__device__ __align__(16) float g_Xt [NSL*SLC];
__device__ __align__(16) float g_X1 [NSL*SLC];
__device__ __align__(16) float g_X2 [NSL*SLC];
__device__ __align__(16) float g_H1a[NSL*SLC];
__device__ __align__(16) float g_H1b[NSL*SLC];
__device__ __align__(16) float g_H2a[NSL*SLC];
__device__ __align__(16) float g_H2b[NSL*SLC];
__device__ __align__(16) float g_R1 [NSL*VN];
__device__ __align__(16) float g_R2 [NSL*VN];
__device__ __align__(16) float g_E  [NSL*ESL];
__device__ __align__(16) float g_ET [NSL*ESL];

__device__ __forceinline__ void fma2(u64 &d, u64 a, u64 b) {
    asm("fma.rn.f32x2 %0, %1, %2, %0;" : "+l"(d) : "l"(a), "l"(b));
}
__device__ __forceinline__ u64 pk2(float x) {
    u64 r; asm("mov.b64 %0, {%1, %1};" : "=l"(r) : "f"(x)); return r;
}
__device__ __forceinline__ float2 up2(u64 a) {
    float2 r; asm("mov.b64 {%0, %1}, %2;" : "=f"(r.x), "=f"(r.y) : "l"(a)); return r;
}
__device__ __forceinline__ unsigned s2u(const void* p) {
    unsigned a;
    asm("{ .reg .u64 t; cvta.to.shared.u64 t, %1; cvt.u32.u64 %0, t; }"
        : "=r"(a) : "l"(p));
    return a;
}
#define CP16(d, s) asm volatile("cp.async.cg.shared.global [%0], [%1], 16;" :: "r"(d), "l"(s))
#define CPCOMMIT() asm volatile("cp.async.commit_group;" ::: "memory")
#define CPWAIT(n)  asm volatile("cp.async.wait_group %0;" :: "n"(n) : "memory")

// transpose x -> g_Xt[s][c][v]; contiguous 48B reads, coalesced scatter.
__global__ __launch_bounds__(256) void k_tr(const float* __restrict__ x) {
    int id = blockIdx.x * 256 + threadIdx.x;  // (n*32+c)*400+v
    if (id >= 409600) return;
    const float4* xp = (const float4*)x;
    float4 a = xp[id * 3], b = xp[id * 3 + 1], c4 = xp[id * 3 + 2];
    float vals[12] = {a.x, a.y, a.z, a.w, b.x, b.y, b.z, b.w,
                      c4.x, c4.y, c4.z, c4.w};
    int n = id / SLC, cv = id - n * SLC;
    float* base = g_Xt + cv;
    #pragma unroll
    for (int l = 0; l < 12; l++)
        base[(size_t)(n * LL + l) * SLC] = vals[l];
}

// X1 = tanh(W1 Xt + b1), X2 = tanh(W2 Xt + b2)
__global__ __launch_bounds__(256) void k_conv(const float* __restrict__ w1,
                                              const float* __restrict__ b1,
                                              const float* __restrict__ w2,
                                              const float* __restrict__ b2) {
    __shared__ float w1s[1024], w2s[1024], b1s[32], b2s[32];
    int s = blockIdx.x, t = threadIdx.x;
    for (int i = t; i < 1024; i += 256) { w1s[i] = w1[i]; w2s[i] = w2[i]; }
    if (t < 32) { b1s[t] = b1[t]; b2s[t] = b2[t]; }
    __syncthreads();
    const float* xt = g_Xt + (size_t)s * SLC;
    for (int i = t; i < SLC; i += 256) {
        int c = i / VN, v = i - c * VN;
        float a1 = b1s[c], a2 = b2s[c];
        #pragma unroll
        for (int k = 0; k < 32; k++) {
            float xv = xt[k * VN + v];
            a1 += w1s[c * 32 + k] * xv;
            a2 += w2s[c * 32 + k] * xv;
        }
        g_X1[(size_t)s * SLC + i] = tanhf(a1);
        g_X2[(size_t)s * SLC + i] = tanhf(a2);
    }
}

// Fused E-builder: z=0 -> E=exp(X1^T X2), R1; z=1 -> ET, R2.
// grid (13, NSL, 2), block 256, 2 CTAs/SM. B staged via cp.async.
__global__ __launch_bounds__(256, 2) void k2(const float* __restrict__ X1p,
                                             const float* __restrict__ X2p,
                                             float* __restrict__ Eo1,
                                             float* __restrict__ Ro1,
                                             float* __restrict__ Eo2,
                                             float* __restrict__ Ro2) {
    __shared__ u64 As2[1024];       // [k][vl] pk2(A), 8KB
    __shared__ float Bs[SLC];       // full B slice, 51.2KB
    __shared__ float red[128];      // [warp][lv]
    int s = blockIdx.y, vbase = blockIdx.x * 32, z = blockIdx.z;
    const float* A = z ? X2p : X1p;
    const float* B = z ? X1p : X2p;
    float* Eo = z ? Eo2 : Eo1;
    float* Ro = z ? Ro2 : Ro1;
    int t = threadIdx.x, lam = t & 31, wp = t >> 5;
    {   // async B stage, overlapped with A pack below
        const float4* Bg = (const float4*)(B + (size_t)s * SLC);
        unsigned bss = s2u(Bs);
        #pragma unroll
        for (int i = 0; i < 13; i++) {
            int idx = t + i * 256;
            if (idx < 3200) CP16(bss + idx * 16, Bg + idx);
        }
        CPCOMMIT();
    }
    for (int i = t; i < 1024; i += 256) {
        int k = i >> 5, vl = i & 31, v = vbase + vl;
        As2[i] = pk2(v < VN ? A[(size_t)s * SLC + k * VN + v] : 0.f);
    }
    CPWAIT(0);
    __syncthreads();
    int half = t >> 7, u = t & 127;
    bool act = (u < 100);
    int w4 = act ? u * 4 : 0;
    int vof = half * 16;
    u64 acc[16][2];
    #pragma unroll
    for (int i = 0; i < 16; i++) { acc[i][0] = 0; acc[i][1] = 0; }
    #pragma unroll 4
    for (int k = 0; k < 32; k++) {
        ull2 bq = *(const ull2*)(Bs + k * VN + w4);
        #pragma unroll
        for (int vp = 0; vp < 8; vp++) {
            ull2 a = *(const ull2*)&As2[k * 32 + vof + 2 * vp];
            fma2(acc[2 * vp][0], a.x, bq.x);
            fma2(acc[2 * vp][1], a.x, bq.y);
            fma2(acc[2 * vp + 1][0], a.y, bq.x);
            fma2(acc[2 * vp + 1][1], a.y, bq.y);
        }
    }
    float prs[16];
    float* Erow = Eo + (size_t)s * ESL;
    #pragma unroll
    for (int lv = 0; lv < 16; lv++) {
        int v = vbase + vof + lv;
        float2 p0 = up2(acc[lv][0]), p1 = up2(acc[lv][1]);
        float4 e;
        e.x = __expf(p0.x); e.y = __expf(p0.y);
        e.z = __expf(p1.x); e.w = __expf(p1.y);
        prs[lv] = act ? (e.x + e.y) + (e.z + e.w) : 0.f;
        if (act && v < VN)
            *(float4*)(Erow + (size_t)v * VN + w4) = e;
    }
    #pragma unroll
    for (int lv = 0; lv < 16; lv++) {
        #pragma unroll
        for (int o = 16; o > 0; o >>= 1)
            prs[lv] += __shfl_xor_sync(0xffffffffu, prs[lv], o);
    }
    if (lam == 0) {
        #pragma unroll
        for (int lv = 0; lv < 16; lv++) red[wp * 16 + lv] = prs[lv];
    }
    __syncthreads();
    if (t < 32) {
        int h = t >> 4, lv = t & 15;
        float sum = red[(h * 4 + 0) * 16 + lv] + red[(h * 4 + 1) * 16 + lv]
                  + red[(h * 4 + 2) * 16 + lv] + red[(h * 4 + 3) * 16 + lv];
        int v = vbase + h * 16 + lv;
        if (v < VN) Ro[(size_t)s * VN + v] = sum;
    }
}

// Fused double diffusion with cp.async double-buffered E staging.
// grid (NSL, 2 sides), block 512, 1 CTA/SM.
// Groups g=t>>7 own channels g*8..g*8+7; u=t&127<100 owns w-quad 4u.
// smem: rinv(1600) + hs2(102400) + ebuf(2*12800) = 129600 B.
__global__ __launch_bounds__(512, 1) void kd(const float* __restrict__ E1,
                                             const float* __restrict__ Rr1,
                                             const float* __restrict__ E2,
                                             const float* __restrict__ Rr2,
                                             float* __restrict__ Ho1a,
                                             float* __restrict__ Ho1b,
                                             float* __restrict__ Ho2a,
                                             float* __restrict__ Ho2b) {
    extern __shared__ float smf[];
    float* rinv = smf;                   // 400 f
    u64*   hs2  = (u64*)(smf + VN);      // 12800 u64
    float* ebuf = (float*)(hs2 + SLC);   // 2 * 3200 f
    int s = blockIdx.x, side = blockIdx.y, t = threadIdx.x;
    const float* Em = side ? E2 : E1;
    const float* Rm = side ? Rr2 : Rr1;
    float* Hoa = side ? Ho2a : Ho1a;
    float* Hob = side ? Ho2b : Ho1b;
    const float* Eb = Em + (size_t)s * ESL;
    const float* Xb = g_Xt + (size_t)s * SLC;
    unsigned ebs = s2u(ebuf);

    // kick tile-0 copy for step 0 immediately (overlaps init)
    {
        const float4* src = (const float4*)Eb;
        unsigned d = ebs + t * 16;
        CP16(d, src + t);
        if (t < 288) CP16(d + 8192, src + 512 + t);
        CPCOMMIT();
    }
    for (int i = t; i < VN; i += 512) rinv[i] = 1.0f / Rm[(size_t)s * VN + i];
    __syncthreads();
    for (int i = t; i < SLC; i += 512)
        hs2[i] = pk2(Xb[i] * rinv[i % VN]);

    int g = t >> 7, u = t & 127;
    bool act = (u < 100);
    int w4 = act ? u * 4 : 0;
    int cb = g * 8;

    for (int step = 0; step < 2; step++) {
        if (step == 1) {   // tile-0 copy for step 1 (buf0 idle since tile 48)
            const float4* src = (const float4*)Eb;
            unsigned d = ebs + t * 16;
            CP16(d, src + t);
            if (t < 288) CP16(d + 8192, src + 512 + t);
            CPCOMMIT();
        }
        u64 acc[8][2];
        #pragma unroll
        for (int c = 0; c < 8; c++) { acc[c][0] = 0; acc[c][1] = 0; }
        for (int tl = 0; tl < 50; tl++) {
            if (tl + 1 < 50) {   // prefetch next tile into other buffer
                const float4* src = (const float4*)(Eb + (size_t)(tl + 1) * 3200);
                unsigned d = ebs + (unsigned)(((tl + 1) & 1) * 12800) + t * 16;
                CP16(d, src + t);
                if (t < 288) CP16(d + 8192, src + 512 + t);
                CPCOMMIT();
                CPWAIT(1);
            } else {
                CPWAIT(0);
            }
            __syncthreads();   // tile data (and hs2 init at tl=0) visible
            const float* EB = ebuf + (tl & 1) * 3200;
            int vb = tl * 8;
            #pragma unroll
            for (int r = 0; r < 8; r += 2) {
                ull2 e0 = *(const ull2*)(EB + r * VN + w4);
                ull2 e1 = *(const ull2*)(EB + (r + 1) * VN + w4);
                #pragma unroll
                for (int c = 0; c < 8; c++) {
                    ull2 h = *(const ull2*)&hs2[(cb + c) * VN + vb + r];
                    fma2(acc[c][0], h.x, e0.x);
                    fma2(acc[c][1], h.x, e0.y);
                    fma2(acc[c][0], h.y, e1.x);
                    fma2(acc[c][1], h.y, e1.y);
                }
            }
            __syncthreads();   // buffer free for reuse
        }
        float* Ob = (step == 0 ? Hoa : Hob) + (size_t)s * SLC;
        if (act) {
            float r0 = rinv[w4], r1_ = rinv[w4 + 1];
            float r2_ = rinv[w4 + 2], r3_ = rinv[w4 + 3];
            #pragma unroll
            for (int c = 0; c < 8; c++) {
                int ch = cb + c;
                float4 xv = *(const float4*)(Xb + ch * VN + w4);
                float2 p0 = up2(acc[c][0]), p1 = up2(acc[c][1]);
                float4 r;
                r.x = 0.05f * xv.x + 0.95f * p0.x;
                r.y = 0.05f * xv.y + 0.95f * p0.y;
                r.z = 0.05f * xv.z + 0.95f * p1.x;
                r.w = 0.05f * xv.w + 0.95f * p1.y;
                *(float4*)(Ob + ch * VN + w4) = r;
                if (step == 0) {
                    hs2[ch * VN + w4 + 0] = pk2(r.x * r0);
                    hs2[ch * VN + w4 + 1] = pk2(r.y * r1_);
                    hs2[ch * VN + w4 + 2] = pk2(r.z * r2_);
                    hs2[ch * VN + w4 + 3] = pk2(r.w * r3_);
                }
            }
        }
        __syncthreads();   // repacked hs2 visible before step 2
    }
}

// out = b1+b2 + (Wm1x+Wm2x)Xt + Wm1a*H1a + Wm1b*H1b + Wm2a*H2a + Wm2b*H2b
// Phase-staged: each source array staged to smem once; acc in registers.
__global__ __launch_bounds__(256, 2) void k_mlp(const float* __restrict__ w1,
                                                const float* __restrict__ b1,
                                                const float* __restrict__ w2,
                                                const float* __restrict__ b2,
                                                float* __restrict__ out) {
    __shared__ float wxc[1024], wa1[2048], wa2[2048], bs[32];
    extern __shared__ float arrbuf[];   // 12800 floats (51200 B)
    int s = blockIdx.x, t = threadIdx.x;
    int n = s / LL, l = s - n * LL;
    for (int i = t; i < 1024; i += 256) {
        int o = i >> 5, c = i & 31;
        wxc[i] = w1[o * 96 + c] + w2[o * 96 + c];
    }
    for (int i = t; i < 2048; i += 256) {
        int o = i >> 6, c = i & 63;
        wa1[i] = w1[o * 96 + 32 + c];
        wa2[i] = w2[o * 96 + 32 + c];
    }
    if (t < 32) bs[t] = b1[t] + b2[t];
    __syncthreads();
    size_t sb = (size_t)s * SLC;
    float4 acc[13];
    #pragma unroll
    for (int i = 0; i < 13; i++) {
        int qd = t + i * 256;
        float bz = (qd < 3200) ? bs[qd / 100] : 0.f;
        acc[i].x = bz; acc[i].y = bz; acc[i].z = bz; acc[i].w = bz;
    }
    float4* ab4 = (float4*)arrbuf;
    #pragma unroll
    for (int ph = 0; ph < 5; ph++) {
        const float* srcp = (ph == 0) ? g_Xt + sb :
                            (ph == 1) ? g_H1a + sb :
                            (ph == 2) ? g_H1b + sb :
                            (ph == 3) ? g_H2a + sb : g_H2b + sb;
        __syncthreads();   // previous phase fully consumed
        const float4* sg = (const float4*)srcp;
        for (int i = t; i < 3200; i += 256) ab4[i] = sg[i];
        __syncthreads();
        #pragma unroll
        for (int i = 0; i < 13; i++) {
            int qd = t + i * 256;
            if (qd < 3200) {
                int o = qd / 100, vq = qd - o * 100;
                const float* ws = (ph == 0) ? &wxc[o * 32] :
                                  (ph == 1) ? &wa1[o * 64] :
                                  (ph == 2) ? &wa1[o * 64 + 32] :
                                  (ph == 3) ? &wa2[o * 64] : &wa2[o * 64 + 32];
                #pragma unroll 8
                for (int c = 0; c < 32; c++) {
                    float w = ws[c];
                    float4 xv = ab4[c * 100 + vq];
                    acc[i].x += w * xv.x; acc[i].y += w * xv.y;
                    acc[i].z += w * xv.z; acc[i].w += w * xv.w;
                }
            }
        }
    }
    #pragma unroll
    for (int i = 0; i < 13; i++) {
        int qd = t + i * 256;
        if (qd < 3200) {
            int o = qd / 100, vq = qd - o * 100;
            int v = vq * 4;
            size_t ob = ((size_t)(n * CH + o) * VN + v) * LL + l;
            out[ob]          = acc[i].x;
            out[ob + LL]     = acc[i].y;
            out[ob + 2 * LL] = acc[i].z;
            out[ob + 3 * LL] = acc[i].w;
        }
    }
}

extern "C" void kernel_launch(void* const* d_in, const int* in_sizes, int n_in,
                              void* d_out, int out_size) {
    const float* x   = (const float*)d_in[0];
    const float* wl1 = (const float*)d_in[1];
    const float* bl1 = (const float*)d_in[2];
    const float* wl2 = (const float*)d_in[3];
    const float* bl2 = (const float*)d_in[4];
    const float* wm1 = (const float*)d_in[5];
    const float* bm1 = (const float*)d_in[6];
    const float* wm2 = (const float*)d_in[7];
    const float* bm2 = (const float*)d_in[8];
    float* out = (float*)d_out;

    const int dsm_kd  = VN * 4 + SLC * 8 + 2 * 3200 * 4;  // 129600
    const int dsm_mlp = SLC * 4;                           // 51200
    static bool attr_done = false;
    if (!attr_done) {
        cudaFuncSetAttribute(kd, cudaFuncAttributeMaxDynamicSharedMemorySize, dsm_kd);
        cudaFuncSetAttribute(k_mlp, cudaFuncAttributeMaxDynamicSharedMemorySize, dsm_mlp);
        attr_done = true;
    }

    float *E, *ET, *R1, *R2, *X1, *X2, *H1a, *H1b, *H2a, *H2b;
    cudaGetSymbolAddress((void**)&E,  g_E);
    cudaGetSymbolAddress((void**)&ET, g_ET);
    cudaGetSymbolAddress((void**)&R1, g_R1);
    cudaGetSymbolAddress((void**)&R2, g_R2);
    cudaGetSymbolAddress((void**)&X1, g_X1);
    cudaGetSymbolAddress((void**)&X2, g_X2);
    cudaGetSymbolAddress((void**)&H1a, g_H1a);
    cudaGetSymbolAddress((void**)&H1b, g_H1b);
    cudaGetSymbolAddress((void**)&H2a, g_H2a);
    cudaGetSymbolAddress((void**)&H2b, g_H2b);

    k_tr<<<1600, 256>>>(x);
    k_conv<<<NSL, 256>>>(wl1, bl1, wl2, bl2);
    k2<<<dim3(13, NSL, 2), 256>>>(X1, X2, E, R1, ET, R2);
    kd<<<dim3(NSL, 2), 512, dsm_kd>>>(E, R1, ET, R2, H1a, H1b, H2a, H2b);
    k_mlp<<<NSL, 256, dsm_mlp>>>(wm1, bm1, wm2, bm2, out);
}

// round 16
// speedup vs baseline: 1.5233x; 1.5233x over previous
#include <cuda_runtime.h>

typedef unsigned long long u64;
typedef ulonglong2 ull2;
#define NSL 384
#define SLC 12800
#define ESL 160000
#define VN  400
#define CH  32
#define LL  12

__device__ __align__(16) float g_Xt [NSL*SLC];
__device__ __align__(16) float g_X1 [NSL*SLC];
__device__ __align__(16) float g_X2 [NSL*SLC];
__device__ __align__(16) float g_H1a[NSL*SLC];
__device__ __align__(16) float g_H1b[NSL*SLC];
__device__ __align__(16) float g_H2a[NSL*SLC];
__device__ __align__(16) float g_H2b[NSL*SLC];
__device__ __align__(16) float g_R1 [NSL*VN];
__device__ __align__(16) float g_R2 [NSL*VN];
__device__ __align__(16) float g_E  [NSL*ESL];
__device__ __align__(16) float g_ET [NSL*ESL];

__device__ __forceinline__ void fma2(u64 &d, u64 a, u64 b) {
    asm("fma.rn.f32x2 %0, %1, %2, %0;" : "+l"(d) : "l"(a), "l"(b));
}
__device__ __forceinline__ u64 pk2(float x) {
    u64 r; asm("mov.b64 %0, {%1, %1};" : "=l"(r) : "f"(x)); return r;
}
__device__ __forceinline__ float2 up2(u64 a) {
    float2 r; asm("mov.b64 {%0, %1}, %2;" : "=f"(r.x), "=f"(r.y) : "l"(a)); return r;
}
__device__ __forceinline__ unsigned s2u(const void* p) {
    unsigned a;
    asm("{ .reg .u64 t; cvta.to.shared.u64 t, %1; cvt.u32.u64 %0, t; }"
        : "=r"(a) : "l"(p));
    return a;
}
#define CP16(d, s) asm volatile("cp.async.cg.shared.global [%0], [%1], 16;" :: "r"(d), "l"(s))
#define CPCOMMIT() asm volatile("cp.async.commit_group;" ::: "memory")
#define CPWAIT(n)  asm volatile("cp.async.wait_group %0;" :: "n"(n) : "memory")

// transpose x -> g_Xt[s][c][v]; contiguous 48B reads, coalesced scatter.
__global__ __launch_bounds__(256) void k_tr(const float* __restrict__ x) {
    int id = blockIdx.x * 256 + threadIdx.x;  // (n*32+c)*400+v
    if (id >= 409600) return;
    const float4* xp = (const float4*)x;
    float4 a = xp[id * 3], b = xp[id * 3 + 1], c4 = xp[id * 3 + 2];
    float vals[12] = {a.x, a.y, a.z, a.w, b.x, b.y, b.z, b.w,
                      c4.x, c4.y, c4.z, c4.w};
    int n = id / SLC, cv = id - n * SLC;
    float* base = g_Xt + cv;
    #pragma unroll
    for (int l = 0; l < 12; l++)
        base[(size_t)(n * LL + l) * SLC] = vals[l];
}

// X1 = tanh(W1 Xt + b1), X2 = tanh(W2 Xt + b2)
__global__ __launch_bounds__(256) void k_conv(const float* __restrict__ w1,
                                              const float* __restrict__ b1,
                                              const float* __restrict__ w2,
                                              const float* __restrict__ b2) {
    __shared__ float w1s[1024], w2s[1024], b1s[32], b2s[32];
    int s = blockIdx.x, t = threadIdx.x;
    for (int i = t; i < 1024; i += 256) { w1s[i] = w1[i]; w2s[i] = w2[i]; }
    if (t < 32) { b1s[t] = b1[t]; b2s[t] = b2[t]; }
    __syncthreads();
    const float* xt = g_Xt + (size_t)s * SLC;
    for (int i = t; i < SLC; i += 256) {
        int c = i / VN, v = i - c * VN;
        float a1 = b1s[c], a2 = b2s[c];
        #pragma unroll
        for (int k = 0; k < 32; k++) {
            float xv = xt[k * VN + v];
            a1 += w1s[c * 32 + k] * xv;
            a2 += w2s[c * 32 + k] * xv;
        }
        g_X1[(size_t)s * SLC + i] = tanhf(a1);
        g_X2[(size_t)s * SLC + i] = tanhf(a2);
    }
}

// Fused E-builder: z=0 -> E=exp(X1^T X2), R1; z=1 -> ET, R2.
// grid (13, NSL, 2), block 256, 2 CTAs/SM. B staged via 4 cp.async groups
// consumed progressively (compute starts after first 8 k-rows land).
__global__ __launch_bounds__(256, 2) void k2(const float* __restrict__ X1p,
                                             const float* __restrict__ X2p,
                                             float* __restrict__ Eo1,
                                             float* __restrict__ Ro1,
                                             float* __restrict__ Eo2,
                                             float* __restrict__ Ro2) {
    __shared__ u64 As2[1024];       // [k][vl] pk2(A), 8KB
    __shared__ float Bs[SLC];       // full B slice, 51.2KB
    __shared__ float red[128];      // [warp][lv]
    int s = blockIdx.y, vbase = blockIdx.x * 32, z = blockIdx.z;
    const float* A = z ? X2p : X1p;
    const float* B = z ? X1p : X2p;
    float* Eo = z ? Eo2 : Eo1;
    float* Ro = z ? Ro2 : Ro1;
    int t = threadIdx.x, lam = t & 31, wp = t >> 5;
    {   // 4 commit groups of 8 k-rows each (800 float4 / group)
        const float4* Bg = (const float4*)(B + (size_t)s * SLC);
        unsigned bss = s2u(Bs);
        #pragma unroll
        for (int ck = 0; ck < 4; ck++) {
            for (int i = t; i < 800; i += 256) {
                int idx = ck * 800 + i;
                CP16(bss + idx * 16, Bg + idx);
            }
            CPCOMMIT();
        }
    }
    for (int i = t; i < 1024; i += 256) {
        int k = i >> 5, vl = i & 31, v = vbase + vl;
        As2[i] = pk2(v < VN ? A[(size_t)s * SLC + k * VN + v] : 0.f);
    }
    int half = t >> 7, u = t & 127;
    bool act = (u < 100);
    int w4 = act ? u * 4 : 0;
    int vof = half * 16;
    u64 acc[16][2];
    #pragma unroll
    for (int i = 0; i < 16; i++) { acc[i][0] = 0; acc[i][1] = 0; }
    #pragma unroll
    for (int ck = 0; ck < 4; ck++) {
        if (ck == 0) CPWAIT(3);
        else if (ck == 1) CPWAIT(2);
        else if (ck == 2) CPWAIT(1);
        else CPWAIT(0);
        __syncthreads();
        #pragma unroll
        for (int kk = 0; kk < 8; kk++) {
            int k = ck * 8 + kk;
            ull2 bq = *(const ull2*)(Bs + k * VN + w4);
            #pragma unroll
            for (int vp = 0; vp < 8; vp++) {
                ull2 a = *(const ull2*)&As2[k * 32 + vof + 2 * vp];
                fma2(acc[2 * vp][0], a.x, bq.x);
                fma2(acc[2 * vp][1], a.x, bq.y);
                fma2(acc[2 * vp + 1][0], a.y, bq.x);
                fma2(acc[2 * vp + 1][1], a.y, bq.y);
            }
        }
    }
    float prs[16];
    float* Erow = Eo + (size_t)s * ESL;
    #pragma unroll
    for (int lv = 0; lv < 16; lv++) {
        int v = vbase + vof + lv;
        float2 p0 = up2(acc[lv][0]), p1 = up2(acc[lv][1]);
        float4 e;
        e.x = __expf(p0.x); e.y = __expf(p0.y);
        e.z = __expf(p1.x); e.w = __expf(p1.y);
        prs[lv] = act ? (e.x + e.y) + (e.z + e.w) : 0.f;
        if (act && v < VN)
            *(float4*)(Erow + (size_t)v * VN + w4) = e;
    }
    #pragma unroll
    for (int lv = 0; lv < 16; lv++) {
        #pragma unroll
        for (int o = 16; o > 0; o >>= 1)
            prs[lv] += __shfl_xor_sync(0xffffffffu, prs[lv], o);
    }
    if (lam == 0) {
        #pragma unroll
        for (int lv = 0; lv < 16; lv++) red[wp * 16 + lv] = prs[lv];
    }
    __syncthreads();
    if (t < 32) {
        int h = t >> 4, lv = t & 15;
        float sum = red[(h * 4 + 0) * 16 + lv] + red[(h * 4 + 1) * 16 + lv]
                  + red[(h * 4 + 2) * 16 + lv] + red[(h * 4 + 3) * 16 + lv];
        int v = vbase + h * 16 + lv;
        if (v < VN) Ro[(size_t)s * VN + v] = sum;
    }
}

// Fused double diffusion: both GDEP steps, all 32 channels resident.
// grid (NSL, 2 sides), block 256; occupancy smem-bound (2 CTAs/SM @104000B),
// no reg cap so the depth-2 E prefetch fits without spills.
// t<128 -> ch 0..15, t>=128 -> ch 16..31; within half u<100 owns w-quad 4u.
__global__ __launch_bounds__(256) void kd(const float* __restrict__ E1,
                                          const float* __restrict__ Rr1,
                                          const float* __restrict__ E2,
                                          const float* __restrict__ Rr2,
                                          float* __restrict__ Ho1a,
                                          float* __restrict__ Ho1b,
                                          float* __restrict__ Ho2a,
                                          float* __restrict__ Ho2b) {
    extern __shared__ float smf[];
    float* rinv = smf;              // 400
    u64* hs2 = (u64*)(smf + VN);    // [32][400] pk2(H/R)
    int s = blockIdx.x, side = blockIdx.y, t = threadIdx.x;
    const float* Em = side ? E2 : E1;
    const float* Rm = side ? Rr2 : Rr1;
    float* Hoa = side ? Ho2a : Ho1a;
    float* Hob = side ? Ho2b : Ho1b;
    for (int i = t; i < VN; i += 256) rinv[i] = 1.0f / Rm[(size_t)s * VN + i];
    __syncthreads();
    const float* Xb = g_Xt + (size_t)s * SLC;
    for (int i = t; i < SLC; i += 256)
        hs2[i] = pk2(Xb[i] * rinv[i % VN]);
    __syncthreads();

    int half = t >> 7, u = t & 127;
    bool act = (u < 100);
    int w4 = act ? u * 4 : 0;
    int cbase = half * 16;
    const float* Eb = Em + (size_t)s * ESL;

    for (int step = 0; step < 2; step++) {
        u64 acc[16][2];
        #pragma unroll
        for (int c = 0; c < 16; c++) { acc[c][0] = 0; acc[c][1] = 0; }
        if (act) {
            // depth-2 software pipeline: rows v..v+1 compute, v+2..v+5 in flight
            ull2 e0a = *(const ull2*)(Eb + w4);
            ull2 e1a = *(const ull2*)(Eb + VN + w4);
            ull2 e0b = *(const ull2*)(Eb + 2 * (size_t)VN + w4);
            ull2 e1b = *(const ull2*)(Eb + 3 * (size_t)VN + w4);
            for (int v = 0; v < VN; v += 2) {
                int vn = (v + 4 < VN) ? v + 4 : 0;
                ull2 n0 = *(const ull2*)(Eb + (size_t)vn * VN + w4);
                ull2 n1 = *(const ull2*)(Eb + (size_t)(vn + 1) * VN + w4);
                #pragma unroll
                for (int c = 0; c < 16; c++) {
                    ull2 h = *(const ull2*)&hs2[(cbase + c) * VN + v];
                    fma2(acc[c][0], h.x, e0a.x);
                    fma2(acc[c][1], h.x, e0a.y);
                    fma2(acc[c][0], h.y, e1a.x);
                    fma2(acc[c][1], h.y, e1a.y);
                }
                e0a = e0b; e1a = e1b; e0b = n0; e1b = n1;
            }
        }
        __syncthreads();   // all reads of hs2 complete before repack
        if (act) {
            float* Ob = (step == 0 ? Hoa : Hob) + (size_t)s * SLC;
            float r0 = rinv[w4], r1_ = rinv[w4 + 1];
            float r2_ = rinv[w4 + 2], r3_ = rinv[w4 + 3];
            #pragma unroll
            for (int c = 0; c < 16; c++) {
                int ch = cbase + c;
                float4 xv = *(const float4*)(Xb + ch * VN + w4);
                float2 p0 = up2(acc[c][0]), p1 = up2(acc[c][1]);
                float4 r;
                r.x = 0.05f * xv.x + 0.95f * p0.x;
                r.y = 0.05f * xv.y + 0.95f * p0.y;
                r.z = 0.05f * xv.z + 0.95f * p1.x;
                r.w = 0.05f * xv.w + 0.95f * p1.y;
                *(float4*)(Ob + ch * VN + w4) = r;
                if (step == 0) {
                    hs2[ch * VN + w4 + 0] = pk2(r.x * r0);
                    hs2[ch * VN + w4 + 1] = pk2(r.y * r1_);
                    hs2[ch * VN + w4 + 2] = pk2(r.z * r2_);
                    hs2[ch * VN + w4 + 3] = pk2(r.w * r3_);
                }
            }
        }
        __syncthreads();   // repacked hs2 visible before step 2
    }
}

// out = b1+b2 + (Wm1x+Wm2x)Xt + Wm1a*H1a + Wm1b*H1b + Wm2a*H2a + Wm2b*H2b
// Phase-staged: each source array staged to smem once; acc in registers.
__global__ __launch_bounds__(256, 2) void k_mlp(const float* __restrict__ w1,
                                                const float* __restrict__ b1,
                                                const float* __restrict__ w2,
                                                const float* __restrict__ b2,
                                                float* __restrict__ out) {
    __shared__ float wxc[1024], wa1[2048], wa2[2048], bs[32];
    extern __shared__ float arrbuf[];   // 12800 floats (51200 B)
    int s = blockIdx.x, t = threadIdx.x;
    int n = s / LL, l = s - n * LL;
    for (int i = t; i < 1024; i += 256) {
        int o = i >> 5, c = i & 31;
        wxc[i] = w1[o * 96 + c] + w2[o * 96 + c];
    }
    for (int i = t; i < 2048; i += 256) {
        int o = i >> 6, c = i & 63;
        wa1[i] = w1[o * 96 + 32 + c];
        wa2[i] = w2[o * 96 + 32 + c];
    }
    if (t < 32) bs[t] = b1[t] + b2[t];
    __syncthreads();
    size_t sb = (size_t)s * SLC;
    float4 acc[13];
    #pragma unroll
    for (int i = 0; i < 13; i++) {
        int qd = t + i * 256;
        float bz = (qd < 3200) ? bs[qd / 100] : 0.f;
        acc[i].x = bz; acc[i].y = bz; acc[i].z = bz; acc[i].w = bz;
    }
    float4* ab4 = (float4*)arrbuf;
    #pragma unroll
    for (int ph = 0; ph < 5; ph++) {
        const float* srcp = (ph == 0) ? g_Xt + sb :
                            (ph == 1) ? g_H1a + sb :
                            (ph == 2) ? g_H1b + sb :
                            (ph == 3) ? g_H2a + sb : g_H2b + sb;
        __syncthreads();   // previous phase fully consumed
        const float4* sg = (const float4*)srcp;
        for (int i = t; i < 3200; i += 256) ab4[i] = sg[i];
        __syncthreads();
        #pragma unroll
        for (int i = 0; i < 13; i++) {
            int qd = t + i * 256;
            if (qd < 3200) {
                int o = qd / 100, vq = qd - o * 100;
                const float* ws = (ph == 0) ? &wxc[o * 32] :
                                  (ph == 1) ? &wa1[o * 64] :
                                  (ph == 2) ? &wa1[o * 64 + 32] :
                                  (ph == 3) ? &wa2[o * 64] : &wa2[o * 64 + 32];
                #pragma unroll 8
                for (int c = 0; c < 32; c++) {
                    float w = ws[c];
                    float4 xv = ab4[c * 100 + vq];
                    acc[i].x += w * xv.x; acc[i].y += w * xv.y;
                    acc[i].z += w * xv.z; acc[i].w += w * xv.w;
                }
            }
        }
    }
    #pragma unroll
    for (int i = 0; i < 13; i++) {
        int qd = t + i * 256;
        if (qd < 3200) {
            int o = qd / 100, vq = qd - o * 100;
            int v = vq * 4;
            size_t ob = ((size_t)(n * CH + o) * VN + v) * LL + l;
            out[ob]          = acc[i].x;
            out[ob + LL]     = acc[i].y;
            out[ob + 2 * LL] = acc[i].z;
            out[ob + 3 * LL] = acc[i].w;
        }
    }
}

extern "C" void kernel_launch(void* const* d_in, const int* in_sizes, int n_in,
                              void* d_out, int out_size) {
    const float* x   = (const float*)d_in[0];
    const float* wl1 = (const float*)d_in[1];
    const float* bl1 = (const float*)d_in[2];
    const float* wl2 = (const float*)d_in[3];
    const float* bl2 = (const float*)d_in[4];
    const float* wm1 = (const float*)d_in[5];
    const float* bm1 = (const float*)d_in[6];
    const float* wm2 = (const float*)d_in[7];
    const float* bm2 = (const float*)d_in[8];
    float* out = (float*)d_out;

    const int dsm_kd  = VN * 4 + SLC * 8;   // 104000
    const int dsm_mlp = SLC * 4;            // 51200
    static bool attr_done = false;
    if (!attr_done) {
        cudaFuncSetAttribute(kd, cudaFuncAttributeMaxDynamicSharedMemorySize, dsm_kd);
        cudaFuncSetAttribute(k_mlp, cudaFuncAttributeMaxDynamicSharedMemorySize, dsm_mlp);
        attr_done = true;
    }

    float *E, *ET, *R1, *R2, *X1, *X2, *H1a, *H1b, *H2a, *H2b;
    cudaGetSymbolAddress((void**)&E,  g_E);
    cudaGetSymbolAddress((void**)&ET, g_ET);
    cudaGetSymbolAddress((void**)&R1, g_R1);
    cudaGetSymbolAddress((void**)&R2, g_R2);
    cudaGetSymbolAddress((void**)&X1, g_X1);
    cudaGetSymbolAddress((void**)&X2, g_X2);
    cudaGetSymbolAddress((void**)&H1a, g_H1a);
    cudaGetSymbolAddress((void**)&H1b, g_H1b);
    cudaGetSymbolAddress((void**)&H2a, g_H2a);
    cudaGetSymbolAddress((void**)&H2b, g_H2b);

    k_tr<<<1600, 256>>>(x);
    k_conv<<<NSL, 256>>>(wl1, bl1, wl2, bl2);
    k2<<<dim3(13, NSL, 2), 256>>>(X1, X2, E, R1, ET, R2);
    kd<<<dim3(NSL, 2), 256, dsm_kd>>>(E, R1, ET, R2, H1a, H1b, H2a, H2b);
    k_mlp<<<NSL, 256, dsm_mlp>>>(wm1, bm1, wm2, bm2, out);
}

// round 17
// speedup vs baseline: 1.7863x; 1.1727x over previous
#include <cuda_runtime.h>

typedef unsigned long long u64;
typedef ulonglong2 ull2;
#define NSL 384
#define SLC 12800
#define ESL 160000
#define VN  400
#define CH  32
#define LL  12

__device__ __align__(16) float g_Xt [NSL*SLC];
__device__ __align__(16) float g_X1 [NSL*SLC];
__device__ __align__(16) float g_X2 [NSL*SLC];
__device__ __align__(16) float g_H1a[NSL*SLC];
__device__ __align__(16) float g_H1b[NSL*SLC];
__device__ __align__(16) float g_H2a[NSL*SLC];
__device__ __align__(16) float g_H2b[NSL*SLC];
__device__ __align__(16) float g_R1 [NSL*VN];
__device__ __align__(16) float g_R2 [NSL*VN];
__device__ __align__(16) float g_E  [NSL*ESL];
__device__ __align__(16) float g_ET [NSL*ESL];

__device__ __forceinline__ void fma2(u64 &d, u64 a, u64 b) {
    asm("fma.rn.f32x2 %0, %1, %2, %0;" : "+l"(d) : "l"(a), "l"(b));
}
__device__ __forceinline__ u64 pk2(float x) {
    u64 r; asm("mov.b64 %0, {%1, %1};" : "=l"(r) : "f"(x)); return r;
}
__device__ __forceinline__ float2 up2(u64 a) {
    float2 r; asm("mov.b64 {%0, %1}, %2;" : "=f"(r.x), "=f"(r.y) : "l"(a)); return r;
}
__device__ __forceinline__ unsigned s2u(const void* p) {
    unsigned a;
    asm("{ .reg .u64 t; cvta.to.shared.u64 t, %1; cvt.u32.u64 %0, t; }"
        : "=r"(a) : "l"(p));
    return a;
}
#define CP16(d, s) asm volatile("cp.async.cg.shared.global [%0], [%1], 16;" :: "r"(d), "l"(s))
#define CPCOMMIT() asm volatile("cp.async.commit_group;" ::: "memory")
#define CPWAIT(n)  asm volatile("cp.async.wait_group %0;" :: "n"(n) : "memory")

// transpose x -> g_Xt[s][c][v]; contiguous 48B reads, coalesced scatter.
__global__ __launch_bounds__(256) void k_tr(const float* __restrict__ x) {
    int id = blockIdx.x * 256 + threadIdx.x;  // (n*32+c)*400+v
    if (id >= 409600) return;
    const float4* xp = (const float4*)x;
    float4 a = xp[id * 3], b = xp[id * 3 + 1], c4 = xp[id * 3 + 2];
    float vals[12] = {a.x, a.y, a.z, a.w, b.x, b.y, b.z, b.w,
                      c4.x, c4.y, c4.z, c4.w};
    int n = id / SLC, cv = id - n * SLC;
    float* base = g_Xt + cv;
    #pragma unroll
    for (int l = 0; l < 12; l++)
        base[(size_t)(n * LL + l) * SLC] = vals[l];
}

// X1 = tanh(W1 Xt + b1), X2 = tanh(W2 Xt + b2)
__global__ __launch_bounds__(256) void k_conv(const float* __restrict__ w1,
                                              const float* __restrict__ b1,
                                              const float* __restrict__ w2,
                                              const float* __restrict__ b2) {
    __shared__ float w1s[1024], w2s[1024], b1s[32], b2s[32];
    int s = blockIdx.x, t = threadIdx.x;
    for (int i = t; i < 1024; i += 256) { w1s[i] = w1[i]; w2s[i] = w2[i]; }
    if (t < 32) { b1s[t] = b1[t]; b2s[t] = b2[t]; }
    __syncthreads();
    const float* xt = g_Xt + (size_t)s * SLC;
    for (int i = t; i < SLC; i += 256) {
        int c = i / VN, v = i - c * VN;
        float a1 = b1s[c], a2 = b2s[c];
        #pragma unroll
        for (int k = 0; k < 32; k++) {
            float xv = xt[k * VN + v];
            a1 += w1s[c * 32 + k] * xv;
            a2 += w2s[c * 32 + k] * xv;
        }
        g_X1[(size_t)s * SLC + i] = tanhf(a1);
        g_X2[(size_t)s * SLC + i] = tanhf(a2);
    }
}

// Fused E-builder: z=0 -> E=exp(X1^T X2), R1; z=1 -> ET, R2.
// grid (13, NSL, 2), block 256, 2 CTAs/SM. B staged via 4 cp.async groups.
__global__ __launch_bounds__(256, 2) void k2(const float* __restrict__ X1p,
                                             const float* __restrict__ X2p,
                                             float* __restrict__ Eo1,
                                             float* __restrict__ Ro1,
                                             float* __restrict__ Eo2,
                                             float* __restrict__ Ro2) {
    __shared__ u64 As2[1024];       // [k][vl] pk2(A), 8KB
    __shared__ float Bs[SLC];       // full B slice, 51.2KB
    __shared__ float red[128];      // [warp][lv]
    int s = blockIdx.y, vbase = blockIdx.x * 32, z = blockIdx.z;
    const float* A = z ? X2p : X1p;
    const float* B = z ? X1p : X2p;
    float* Eo = z ? Eo2 : Eo1;
    float* Ro = z ? Ro2 : Ro1;
    int t = threadIdx.x, lam = t & 31, wp = t >> 5;
    {   // 4 commit groups of 8 k-rows each (800 float4 / group)
        const float4* Bg = (const float4*)(B + (size_t)s * SLC);
        unsigned bss = s2u(Bs);
        #pragma unroll
        for (int ck = 0; ck < 4; ck++) {
            for (int i = t; i < 800; i += 256) {
                int idx = ck * 800 + i;
                CP16(bss + idx * 16, Bg + idx);
            }
            CPCOMMIT();
        }
    }
    for (int i = t; i < 1024; i += 256) {
        int k = i >> 5, vl = i & 31, v = vbase + vl;
        As2[i] = pk2(v < VN ? A[(size_t)s * SLC + k * VN + v] : 0.f);
    }
    int half = t >> 7, u = t & 127;
    bool act = (u < 100);
    int w4 = act ? u * 4 : 0;
    int vof = half * 16;
    u64 acc[16][2];
    #pragma unroll
    for (int i = 0; i < 16; i++) { acc[i][0] = 0; acc[i][1] = 0; }
    #pragma unroll
    for (int ck = 0; ck < 4; ck++) {
        if (ck == 0) CPWAIT(3);
        else if (ck == 1) CPWAIT(2);
        else if (ck == 2) CPWAIT(1);
        else CPWAIT(0);
        __syncthreads();
        #pragma unroll
        for (int kk = 0; kk < 8; kk++) {
            int k = ck * 8 + kk;
            ull2 bq = *(const ull2*)(Bs + k * VN + w4);
            #pragma unroll
            for (int vp = 0; vp < 8; vp++) {
                ull2 a = *(const ull2*)&As2[k * 32 + vof + 2 * vp];
                fma2(acc[2 * vp][0], a.x, bq.x);
                fma2(acc[2 * vp][1], a.x, bq.y);
                fma2(acc[2 * vp + 1][0], a.y, bq.x);
                fma2(acc[2 * vp + 1][1], a.y, bq.y);
            }
        }
    }
    float prs[16];
    float* Erow = Eo + (size_t)s * ESL;
    #pragma unroll
    for (int lv = 0; lv < 16; lv++) {
        int v = vbase + vof + lv;
        float2 p0 = up2(acc[lv][0]), p1 = up2(acc[lv][1]);
        float4 e;
        e.x = __expf(p0.x); e.y = __expf(p0.y);
        e.z = __expf(p1.x); e.w = __expf(p1.y);
        prs[lv] = act ? (e.x + e.y) + (e.z + e.w) : 0.f;
        if (act && v < VN)
            *(float4*)(Erow + (size_t)v * VN + w4) = e;
    }
    #pragma unroll
    for (int lv = 0; lv < 16; lv++) {
        #pragma unroll
        for (int o = 16; o > 0; o >>= 1)
            prs[lv] += __shfl_xor_sync(0xffffffffu, prs[lv], o);
    }
    if (lam == 0) {
        #pragma unroll
        for (int lv = 0; lv < 16; lv++) red[wp * 16 + lv] = prs[lv];
    }
    __syncthreads();
    if (t < 32) {
        int h = t >> 4, lv = t & 15;
        float sum = red[(h * 4 + 0) * 16 + lv] + red[(h * 4 + 1) * 16 + lv]
                  + red[(h * 4 + 2) * 16 + lv] + red[(h * 4 + 3) * 16 + lv];
        int v = vbase + h * 16 + lv;
        if (v < VN) Ro[(size_t)s * VN + v] = sum;
    }
}

// Fused double diffusion with PER-WARP cp.async E rings (no mainloop barriers).
// grid (NSL, 2 sides), block 256, 2 CTAs/SM.
// t<128 -> ch 0..15, t>=128 -> ch 16..31; u=t&127 owns w-quad 4u (clamped pads).
// dsm = (400 + 12800 + 8192)*4 = 85568 B: rinv + h(float) + 8 warp-rings.
__global__ __launch_bounds__(256, 2) void kd(const float* __restrict__ E1,
                                             const float* __restrict__ Rr1,
                                             const float* __restrict__ E2,
                                             const float* __restrict__ Rr2,
                                             float* __restrict__ Ho1a,
                                             float* __restrict__ Ho1b,
                                             float* __restrict__ Ho2a,
                                             float* __restrict__ Ho2b) {
    extern __shared__ float smf[];
    float* rinv  = smf;                    // 400 floats
    float* hsf   = smf + VN;               // [32][400] H/R (float)
    float* ering = smf + VN + SLC;         // 8 warps x 4 stages x 256 floats
    int s = blockIdx.x, side = blockIdx.y, t = threadIdx.x;
    const float* Em = side ? E2 : E1;
    const float* Rm = side ? Rr2 : Rr1;
    float* Hoa = side ? Ho2a : Ho1a;
    float* Hob = side ? Ho2b : Ho1b;
    const float* Eb = Em + (size_t)s * ESL;
    const float* Xb = g_Xt + (size_t)s * SLC;

    for (int i = t; i < VN; i += 256) rinv[i] = 1.0f / Rm[(size_t)s * VN + i];
    __syncthreads();
    for (int i = t; i < SLC; i += 256)
        hsf[i] = Xb[i] * rinv[i % VN];

    int wp = t >> 5, lane = t & 31, half = t >> 7, u = t & 127;
    bool act = (u < 100);
    int w4  = 4 * u;                       // logical w (store guard uses this)
    int w4r = act ? w4 : 384;              // clamped source for pad lanes
    int cbase = half * 16;
    float* ringw = ering + wp * 1024;      // this warp's ring (floats)
    unsigned ringb = s2u(ringw);
    unsigned lb = lane * 16;               // lane byte offset in 512B segment

    // prologue: fill stages 0..3 with v-pairs 0..3 (4 commit groups)
    #pragma unroll
    for (int vp = 0; vp < 4; vp++) {
        const float* r0 = Eb + (size_t)(2 * vp) * VN + w4r;
        const float* r1 = Eb + (size_t)(2 * vp + 1) * VN + w4r;
        CP16(ringb + vp * 1024 + lb, r0);
        CP16(ringb + vp * 1024 + 512 + lb, r1);
        CPCOMMIT();
    }
    __syncthreads();   // hsf init complete (rings are per-warp, no sync needed for them)

    for (int step = 0; step < 2; step++) {
        u64 acc[16][2];
        #pragma unroll
        for (int c = 0; c < 16; c++) { acc[c][0] = 0; acc[c][1] = 0; }
        for (int vp = 0; vp < 200; vp++) {
            int st = vp & 3;
            CPWAIT(3);   // stage st's copy complete (per-thread wait, no barrier)
            const float* EB = ringw + st * 256;
            ull2 e0 = *(const ull2*)(EB + lane * 4);
            ull2 e1 = *(const ull2*)(EB + 128 + lane * 4);
            int v2 = 2 * vp;
            #pragma unroll
            for (int c = 0; c < 16; c++) {
                float2 h = *(const float2*)&hsf[(cbase + c) * VN + v2];
                u64 hx = pk2(h.x), hy = pk2(h.y);
                fma2(acc[c][0], hx, e0.x);
                fma2(acc[c][1], hx, e0.y);
                fma2(acc[c][0], hy, e1.x);
                fma2(acc[c][1], hy, e1.y);
            }
            // refill this stage with v-pair vp+4 (wraps into next step's rows)
            int vn = vp + 4;
            int v0 = 2 * vn; if (v0 >= VN) v0 -= VN;
            const float* r0 = Eb + (size_t)v0 * VN + w4r;
            const float* r1 = Eb + (size_t)(v0 + 1) * VN + w4r;
            CP16(ringb + st * 1024 + lb, r0);
            CP16(ringb + st * 1024 + 512 + lb, r1);
            CPCOMMIT();
        }
        __syncthreads();   // all hsf reads of this step done before repack
        if (act) {
            float* Ob = (step == 0 ? Hoa : Hob) + (size_t)s * SLC;
            float r0 = rinv[w4], r1_ = rinv[w4 + 1];
            float r2_ = rinv[w4 + 2], r3_ = rinv[w4 + 3];
            #pragma unroll
            for (int c = 0; c < 16; c++) {
                int ch = cbase + c;
                float4 xv = *(const float4*)(Xb + ch * VN + w4);
                float2 p0 = up2(acc[c][0]), p1 = up2(acc[c][1]);
                float4 r;
                r.x = 0.05f * xv.x + 0.95f * p0.x;
                r.y = 0.05f * xv.y + 0.95f * p0.y;
                r.z = 0.05f * xv.z + 0.95f * p1.x;
                r.w = 0.05f * xv.w + 0.95f * p1.y;
                *(float4*)(Ob + ch * VN + w4) = r;
                if (step == 0) {
                    hsf[ch * VN + w4 + 0] = r.x * r0;
                    hsf[ch * VN + w4 + 1] = r.y * r1_;
                    hsf[ch * VN + w4 + 2] = r.z * r2_;
                    hsf[ch * VN + w4 + 3] = r.w * r3_;
                }
            }
        }
        __syncthreads();   // repacked hsf visible before step 2
    }
    CPWAIT(0);   // drain dangling ring copies before exit
}

// out = b1+b2 + (Wm1x+Wm2x)Xt + Wm1a*H1a + Wm1b*H1b + Wm2a*H2a + Wm2b*H2b
// Phase-staged: each source array staged to smem once; acc in registers.
__global__ __launch_bounds__(256, 2) void k_mlp(const float* __restrict__ w1,
                                                const float* __restrict__ b1,
                                                const float* __restrict__ w2,
                                                const float* __restrict__ b2,
                                                float* __restrict__ out) {
    __shared__ float wxc[1024], wa1[2048], wa2[2048], bs[32];
    extern __shared__ float arrbuf[];   // 12800 floats (51200 B)
    int s = blockIdx.x, t = threadIdx.x;
    int n = s / LL, l = s - n * LL;
    for (int i = t; i < 1024; i += 256) {
        int o = i >> 5, c = i & 31;
        wxc[i] = w1[o * 96 + c] + w2[o * 96 + c];
    }
    for (int i = t; i < 2048; i += 256) {
        int o = i >> 6, c = i & 63;
        wa1[i] = w1[o * 96 + 32 + c];
        wa2[i] = w2[o * 96 + 32 + c];
    }
    if (t < 32) bs[t] = b1[t] + b2[t];
    __syncthreads();
    size_t sb = (size_t)s * SLC;
    float4 acc[13];
    #pragma unroll
    for (int i = 0; i < 13; i++) {
        int qd = t + i * 256;
        float bz = (qd < 3200) ? bs[qd / 100] : 0.f;
        acc[i].x = bz; acc[i].y = bz; acc[i].z = bz; acc[i].w = bz;
    }
    float4* ab4 = (float4*)arrbuf;
    #pragma unroll
    for (int ph = 0; ph < 5; ph++) {
        const float* srcp = (ph == 0) ? g_Xt + sb :
                            (ph == 1) ? g_H1a + sb :
                            (ph == 2) ? g_H1b + sb :
                            (ph == 3) ? g_H2a + sb : g_H2b + sb;
        __syncthreads();   // previous phase fully consumed
        const float4* sg = (const float4*)srcp;
        for (int i = t; i < 3200; i += 256) ab4[i] = sg[i];
        __syncthreads();
        #pragma unroll
        for (int i = 0; i < 13; i++) {
            int qd = t + i * 256;
            if (qd < 3200) {
                int o = qd / 100, vq = qd - o * 100;
                const float* ws = (ph == 0) ? &wxc[o * 32] :
                                  (ph == 1) ? &wa1[o * 64] :
                                  (ph == 2) ? &wa1[o * 64 + 32] :
                                  (ph == 3) ? &wa2[o * 64] : &wa2[o * 64 + 32];
                #pragma unroll 8
                for (int c = 0; c < 32; c++) {
                    float w = ws[c];
                    float4 xv = ab4[c * 100 + vq];
                    acc[i].x += w * xv.x; acc[i].y += w * xv.y;
                    acc[i].z += w * xv.z; acc[i].w += w * xv.w;
                }
            }
        }
    }
    #pragma unroll
    for (int i = 0; i < 13; i++) {
        int qd = t + i * 256;
        if (qd < 3200) {
            int o = qd / 100, vq = qd - o * 100;
            int v = vq * 4;
            size_t ob = ((size_t)(n * CH + o) * VN + v) * LL + l;
            out[ob]          = acc[i].x;
            out[ob + LL]     = acc[i].y;
            out[ob + 2 * LL] = acc[i].z;
            out[ob + 3 * LL] = acc[i].w;
        }
    }
}

extern "C" void kernel_launch(void* const* d_in, const int* in_sizes, int n_in,
                              void* d_out, int out_size) {
    const float* x   = (const float*)d_in[0];
    const float* wl1 = (const float*)d_in[1];
    const float* bl1 = (const float*)d_in[2];
    const float* wl2 = (const float*)d_in[3];
    const float* bl2 = (const float*)d_in[4];
    const float* wm1 = (const float*)d_in[5];
    const float* bm1 = (const float*)d_in[6];
    const float* wm2 = (const float*)d_in[7];
    const float* bm2 = (const float*)d_in[8];
    float* out = (float*)d_out;

    const int dsm_kd  = (VN + SLC + 8192) * 4;   // 85568
    const int dsm_mlp = SLC * 4;                  // 51200
    static bool attr_done = false;
    if (!attr_done) {
        cudaFuncSetAttribute(kd, cudaFuncAttributeMaxDynamicSharedMemorySize, dsm_kd);
        cudaFuncSetAttribute(k_mlp, cudaFuncAttributeMaxDynamicSharedMemorySize, dsm_mlp);
        attr_done = true;
    }

    float *E, *ET, *R1, *R2, *X1, *X2, *H1a, *H1b, *H2a, *H2b;
    cudaGetSymbolAddress((void**)&E,  g_E);
    cudaGetSymbolAddress((void**)&ET, g_ET);
    cudaGetSymbolAddress((void**)&R1, g_R1);
    cudaGetSymbolAddress((void**)&R2, g_R2);
    cudaGetSymbolAddress((void**)&X1, g_X1);
    cudaGetSymbolAddress((void**)&X2, g_X2);
    cudaGetSymbolAddress((void**)&H1a, g_H1a);
    cudaGetSymbolAddress((void**)&H1b, g_H1b);
    cudaGetSymbolAddress((void**)&H2a, g_H2a);
    cudaGetSymbolAddress((void**)&H2b, g_H2b);

    k_tr<<<1600, 256>>>(x);
    k_conv<<<NSL, 256>>>(wl1, bl1, wl2, bl2);
    k2<<<dim3(13, NSL, 2), 256>>>(X1, X2, E, R1, ET, R2);
    kd<<<dim3(NSL, 2), 256, dsm_kd>>>(E, R1, ET, R2, H1a, H1b, H2a, H2b);
    k_mlp<<<NSL, 256, dsm_mlp>>>(wm1, bm1, wm2, bm2, out);
}